// round 15
// baseline (speedup 1.0000x reference)
#include <cuda_runtime.h>

#define NN 100000
#define D 64
#define EMAX 1250000
#define NB 391            // (NN + 255) / 256
#define ISTRIDE 68        // D + 4: rows stay 16B-aligned for LDS.128
#define GEMM_SMEM (D * D * 4 + 128 * ISTRIDE * 4)   // 16384 + 34816 = 51200 B

// Scratch (allocation-free rule: __device__ globals)
__device__ float g_aggF[NN * D];     // mean over in-neighbors  (dst-indexed)
__device__ float g_aggB[NN * D];     // mean over out-neighbors (src-indexed)
__device__ float g_h[NN * D];        // layer-1 output
__device__ int   g_degD[NN], g_degS[NN];
__device__ int   g_rowD[NN + 1], g_rowS[NN + 1];
__device__ int   g_curD[NN], g_curS[NN];
__device__ int   g_adjD[EMAX], g_adjS[EMAX];
__device__ int   g_bsumD[512], g_bsumS[512], g_boffD[512], g_boffS[512];

// ---------------------------------------------------------------------------
__global__ void init_kernel() {
    int i = blockIdx.x * blockDim.x + threadIdx.x;
    if (i < NN) { g_degD[i] = 0; g_degS[i] = 0; }
}

__global__ void degree_kernel(const int* __restrict__ src,
                              const int* __restrict__ dst, int E) {
    int e = blockIdx.x * blockDim.x + threadIdx.x;
    if (e < E) {
        atomicAdd(&g_degS[src[e]], 1);
        atomicAdd(&g_degD[dst[e]], 1);
    }
}

// --- 3-kernel exclusive scan over degrees (both directions at once) --------
__global__ void scan1_kernel() {
    __shared__ int sD[256], sS[256];
    int t = threadIdx.x, i = blockIdx.x * 256 + t;
    int dD = (i < NN) ? g_degD[i] : 0;
    int dS = (i < NN) ? g_degS[i] : 0;
    sD[t] = dD; sS[t] = dS; __syncthreads();
    for (int off = 1; off < 256; off <<= 1) {
        int vD = 0, vS = 0;
        if (t >= off) { vD = sD[t - off]; vS = sS[t - off]; }
        __syncthreads();
        if (t >= off) { sD[t] += vD; sS[t] += vS; }
        __syncthreads();
    }
    if (i < NN) { g_rowD[i] = sD[t] - dD; g_rowS[i] = sS[t] - dS; }
    if (t == 255) { g_bsumD[blockIdx.x] = sD[255]; g_bsumS[blockIdx.x] = sS[255]; }
}

__global__ void scan2_kernel(int nb) {
    __shared__ int sD[512], sS[512];
    int t = threadIdx.x;
    int vD = (t < nb) ? g_bsumD[t] : 0;
    int vS = (t < nb) ? g_bsumS[t] : 0;
    sD[t] = vD; sS[t] = vS; __syncthreads();
    for (int off = 1; off < 512; off <<= 1) {
        int aD = 0, aS = 0;
        if (t >= off) { aD = sD[t - off]; aS = sS[t - off]; }
        __syncthreads();
        if (t >= off) { sD[t] += aD; sS[t] += aS; }
        __syncthreads();
    }
    if (t < nb) { g_boffD[t] = sD[t] - vD; g_boffS[t] = sS[t] - vS; }
}

__global__ void scan3_kernel(int E) {
    int t = threadIdx.x, i = blockIdx.x * 256 + t;
    if (i < NN) {
        int rD = g_rowD[i] + g_boffD[blockIdx.x];
        int rS = g_rowS[i] + g_boffS[blockIdx.x];
        g_rowD[i] = rD; g_rowS[i] = rS;
        g_curD[i] = rD; g_curS[i] = rS;
    }
    if (i == 0) { g_rowD[NN] = E; g_rowS[NN] = E; }
}

__global__ void fill_kernel(const int* __restrict__ src,
                            const int* __restrict__ dst, int E) {
    int e = blockIdx.x * blockDim.x + threadIdx.x;
    if (e < E) {
        int s = src[e], d = dst[e];
        int pD = atomicAdd(&g_curD[d], 1); g_adjD[pD] = s;
        int pS = atomicAdd(&g_curS[s], 1); g_adjS[pS] = d;
    }
}

// ---------------------------------------------------------------------------
// CSR gather-mean: half-warp (16 lanes) per node, float4 per lane.
// ---------------------------------------------------------------------------
__global__ void gather_kernel(const float* __restrict__ h,
                              const int* __restrict__ rowptr,
                              const int* __restrict__ adj,
                              float* __restrict__ out) {
    int tid = blockIdx.x * blockDim.x + threadIdx.x;
    int v = tid >> 4;
    if (v >= NN) return;
    int c = (tid & 15) << 2;

    int p0 = __ldg(rowptr + v), p1 = __ldg(rowptr + v + 1);
    float4 acc = make_float4(0.f, 0.f, 0.f, 0.f);
    int j = p0;
    for (; j + 4 <= p1; j += 4) {
        int u0 = __ldg(adj + j),     u1 = __ldg(adj + j + 1);
        int u2 = __ldg(adj + j + 2), u3 = __ldg(adj + j + 3);
        float4 a = *(const float4*)(h + u0 * D + c);
        float4 b = *(const float4*)(h + u1 * D + c);
        float4 e = *(const float4*)(h + u2 * D + c);
        float4 f = *(const float4*)(h + u3 * D + c);
        acc.x += (a.x + b.x) + (e.x + f.x);
        acc.y += (a.y + b.y) + (e.y + f.y);
        acc.z += (a.z + b.z) + (e.z + f.z);
        acc.w += (a.w + b.w) + (e.w + f.w);
    }
    for (; j < p1; j++) {
        int u = __ldg(adj + j);
        float4 a = *(const float4*)(h + u * D + c);
        acc.x += a.x; acc.y += a.y; acc.z += a.z; acc.w += a.w;
    }
    float inv = (p1 > p0) ? 1.0f / (float)(p1 - p0) : 0.f;
    acc.x *= inv; acc.y *= inv; acc.z *= inv; acc.w *= inv;
    *(float4*)(out + v * D + c) = acc;
}

// ---------------------------------------------------------------------------
// Fused GEMM: out = relu( x@Wr + aggF@W1 + aggB@W2 + b )
// Tile 128 rows x 64 cols, 256 threads: 8 cols x 4 rows per thread.
// W loaded as ulonglong2 (LDS.128 -> 2 packed f32x2, zero pack-movs).
// ---------------------------------------------------------------------------
__global__ __launch_bounds__(256) void gemm_kernel(
    const float* __restrict__ X,
    const float* __restrict__ Wr, const float* __restrict__ W1,
    const float* __restrict__ W2, const float* __restrict__ bias,
    float* __restrict__ out, int n)
{
    extern __shared__ float smem[];
    float* Wsm  = smem;                 // D*D floats, [k][j]
    float* Insm = smem + D * D;         // 128*ISTRIDE floats, [row][k]

    int tid = threadIdx.x;
    int tx = tid & 7;          // col group: 8 cols, c0 = tx*8
    int ty = tid >> 3;         // 0..31: rows ty*4 .. ty*4+3
    int rowBase = blockIdx.x * 128;

    unsigned long long acc[4][4];      // [row r][col pair p]
#pragma unroll
    for (int r = 0; r < 4; r++)
#pragma unroll
        for (int p = 0; p < 4; p++) acc[r][p] = 0ULL;

    const float* ins[3] = { X, g_aggF, g_aggB };
    const float* ws[3]  = { Wr, W1, W2 };

    for (int chunk = 0; chunk < 3; chunk++) {
        __syncthreads();
        // --- load 64x64 weight chunk (1024 float4, coalesced) ---
        const float* W = ws[chunk];
#pragma unroll
        for (int i = 0; i < 4; i++) {
            int idx = tid + i * 256;
            ((float4*)Wsm)[idx] = ((const float4*)W)[idx];
        }
        // --- load 128x64 input tile (2048 float4) ---
        const float* In = ins[chunk];
#pragma unroll
        for (int i = 0; i < 8; i++) {
            int v = tid + i * 256;
            int row = v >> 4;
            int c4 = (v & 15) << 2;
            int grow = rowBase + row;
            float4 val = make_float4(0.f, 0.f, 0.f, 0.f);
            if (grow < n) val = *(const float4*)(In + grow * D + c4);
            *(float4*)&Insm[row * ISTRIDE + c4] = val;
        }
        __syncthreads();

#pragma unroll 2
        for (int k = 0; k < D; k += 4) {
            float4 a4[4];
#pragma unroll
            for (int r = 0; r < 4; r++)
                a4[r] = *(const float4*)&Insm[(ty * 4 + r) * ISTRIDE + k];

#pragma unroll
            for (int kk = 0; kk < 4; kk++) {
                // 8 W cols for this k-row: 2x LDS.128 -> 4 packed f32x2
                const float* wrow = &Wsm[(k + kk) * D + (tx << 3)];
                ulonglong2 wA = *(const ulonglong2*)(wrow);       // pairs 0,1
                ulonglong2 wB = *(const ulonglong2*)(wrow + 4);   // pairs 2,3
#pragma unroll
                for (int r = 0; r < 4; r++) {
                    float av = (kk == 0) ? a4[r].x : (kk == 1) ? a4[r].y
                             : (kk == 2) ? a4[r].z : a4[r].w;
                    unsigned long long a2;
                    asm("mov.b64 %0, {%1, %1};" : "=l"(a2) : "f"(av));
                    asm("fma.rn.f32x2 %0, %1, %2, %0;" : "+l"(acc[r][0]) : "l"(a2), "l"(wA.x));
                    asm("fma.rn.f32x2 %0, %1, %2, %0;" : "+l"(acc[r][1]) : "l"(a2), "l"(wA.y));
                    asm("fma.rn.f32x2 %0, %1, %2, %0;" : "+l"(acc[r][2]) : "l"(a2), "l"(wB.x));
                    asm("fma.rn.f32x2 %0, %1, %2, %0;" : "+l"(acc[r][3]) : "l"(a2), "l"(wB.y));
                }
            }
        }
    }

    // --- epilogue: + bias, relu, store (8 cols per thread) ---
    int c0 = tx << 3;
    float4 bA = *(const float4*)(bias + c0);
    float4 bB = *(const float4*)(bias + c0 + 4);
#pragma unroll
    for (int r = 0; r < 4; r++) {
        int grow = rowBase + ty * 4 + r;
        if (grow < n) {
            float f[8];
            asm("mov.b64 {%0, %1}, %2;" : "=f"(f[0]), "=f"(f[1]) : "l"(acc[r][0]));
            asm("mov.b64 {%0, %1}, %2;" : "=f"(f[2]), "=f"(f[3]) : "l"(acc[r][1]));
            asm("mov.b64 {%0, %1}, %2;" : "=f"(f[4]), "=f"(f[5]) : "l"(acc[r][2]));
            asm("mov.b64 {%0, %1}, %2;" : "=f"(f[6]), "=f"(f[7]) : "l"(acc[r][3]));
            float4 o1, o2;
            o1.x = fmaxf(f[0] + bA.x, 0.f); o1.y = fmaxf(f[1] + bA.y, 0.f);
            o1.z = fmaxf(f[2] + bA.z, 0.f); o1.w = fmaxf(f[3] + bA.w, 0.f);
            o2.x = fmaxf(f[4] + bB.x, 0.f); o2.y = fmaxf(f[5] + bB.y, 0.f);
            o2.z = fmaxf(f[6] + bB.z, 0.f); o2.w = fmaxf(f[7] + bB.w, 0.f);
            *(float4*)(out + grow * D + c0)     = o1;
            *(float4*)(out + grow * D + c0 + 4) = o2;
        }
    }
}

// ---------------------------------------------------------------------------
extern "C" void kernel_launch(void* const* d_in, const int* in_sizes, int n_in,
                              void* d_out, int out_size) {
    const float* x    = (const float*)d_in[0];
    const int*   ei   = (const int*)d_in[1];
    const float* W1_0 = (const float*)d_in[2];
    const float* W2_0 = (const float*)d_in[3];
    const float* Wr_0 = (const float*)d_in[4];
    const float* br_0 = (const float*)d_in[5];
    const float* W1_1 = (const float*)d_in[6];
    const float* W2_1 = (const float*)d_in[7];
    const float* Wr_1 = (const float*)d_in[8];
    const float* br_1 = (const float*)d_in[9];
    float* out = (float*)d_out;

    int E = in_sizes[1] / 2;
    const int* src = ei;
    const int* dst = ei + E;
    int n = in_sizes[0] / D;

    float* hbuf = nullptr;
    cudaGetSymbolAddress((void**)&hbuf, g_h);

    float* aggF = nullptr; float* aggB = nullptr;
    cudaGetSymbolAddress((void**)&aggF, g_aggF);
    cudaGetSymbolAddress((void**)&aggB, g_aggB);
    int* rowD = nullptr; int* rowS = nullptr; int* adjD = nullptr; int* adjS = nullptr;
    cudaGetSymbolAddress((void**)&rowD, g_rowD);
    cudaGetSymbolAddress((void**)&rowS, g_rowS);
    cudaGetSymbolAddress((void**)&adjD, g_adjD);
    cudaGetSymbolAddress((void**)&adjS, g_adjS);

    cudaFuncSetAttribute(gemm_kernel,
                         cudaFuncAttributeMaxDynamicSharedMemorySize, GEMM_SMEM);

    const int eblocks = (E + 255) / 256;
    const int gthreads = NN * 16;
    const int gablocks = (gthreads + 255) / 256;
    const int gemmblocks = (n + 127) / 128;

    // ---- Build CSR (both directions) once; reused by both layers ----
    init_kernel<<<NB, 256>>>();
    degree_kernel<<<eblocks, 256>>>(src, dst, E);
    scan1_kernel<<<NB, 256>>>();
    scan2_kernel<<<1, 512>>>(NB);
    scan3_kernel<<<NB, 256>>>(E);
    fill_kernel<<<eblocks, 256>>>(src, dst, E);

    // ---- Layer 0 ----
    gather_kernel<<<gablocks, 256>>>(x, rowD, adjD, aggF);
    gather_kernel<<<gablocks, 256>>>(x, rowS, adjS, aggB);
    gemm_kernel<<<gemmblocks, 256, GEMM_SMEM>>>(x, Wr_0, W1_0, W2_0, br_0, hbuf, n);

    // ---- Layer 1 ----
    gather_kernel<<<gablocks, 256>>>(hbuf, rowD, adjD, aggF);
    gather_kernel<<<gablocks, 256>>>(hbuf, rowS, adjS, aggB);
    gemm_kernel<<<gemmblocks, 256, GEMM_SMEM>>>(hbuf, Wr_1, W1_1, W2_1, br_1, out, n);
}